// round 1
// baseline (speedup 1.0000x reference)
#include <cuda_runtime.h>

#define EPS 0.1f
#define BB 64
#define II 1024
#define HH 4096
#define OO 256

// ---------------------------------------------------------------------------
// K1: W1_norm[j] = sum_i |W1[j,i]|   (H blocks, 256 threads)
// ---------------------------------------------------------------------------
__device__ float g_w1norm[HH];

__global__ void k_w1norm(const float* __restrict__ W1) {
    const int row = blockIdx.x;
    const float4* r = reinterpret_cast<const float4*>(W1 + (size_t)row * II);
    float s = 0.f;
    // II/4 = 256 float4, one per thread
    float4 v = r[threadIdx.x];
    s = fabsf(v.x) + fabsf(v.y) + fabsf(v.z) + fabsf(v.w);

    __shared__ float sm[8];
    #pragma unroll
    for (int o = 16; o; o >>= 1) s += __shfl_down_sync(0xffffffffu, s, o);
    if ((threadIdx.x & 31) == 0) sm[threadIdx.x >> 5] = s;
    __syncthreads();
    if (threadIdx.x < 8) {
        s = sm[threadIdx.x];
        #pragma unroll
        for (int o = 4; o; o >>= 1) s += __shfl_down_sync(0xffu, s, o);
        if (threadIdx.x == 0) g_w1norm[row] = s;
    }
}

// ---------------------------------------------------------------------------
// K2: nn_output[b,i] = 4096 * sum_j W2[i,j] + bias2[i]  (batch-independent)
//     (O blocks, 256 threads)
// ---------------------------------------------------------------------------
__global__ void k_nnout(const float* __restrict__ W2,
                        const float* __restrict__ bias2,
                        float* __restrict__ out_nn) {
    const int i = blockIdx.x;
    const float4* r = reinterpret_cast<const float4*>(W2 + (size_t)i * HH);
    float s = 0.f;
    // HH/4 = 1024 float4, 4 per thread
    #pragma unroll
    for (int k = 0; k < 4; k++) {
        float4 v = r[threadIdx.x + k * 256];
        s += v.x + v.y + v.z + v.w;
    }
    __shared__ float sm[8];
    #pragma unroll
    for (int o = 16; o; o >>= 1) s += __shfl_down_sync(0xffffffffu, s, o);
    if ((threadIdx.x & 31) == 0) sm[threadIdx.x >> 5] = s;
    __syncthreads();
    __shared__ float total;
    if (threadIdx.x < 8) {
        float t = sm[threadIdx.x];
        #pragma unroll
        for (int o = 4; o; o >>= 1) t += __shfl_down_sync(0xffu, t, o);
        if (threadIdx.x == 0) total = t * (float)HH + bias2[i];
    }
    __syncthreads();
    // fan out to all 64 batch rows
    if (threadIdx.x < BB) {
        out_nn[(size_t)threadIdx.x * OO + i] = total;
    }
}

// ---------------------------------------------------------------------------
// K3: pert[b,i,j] = -EPS * yf[b,i] * sign(W2[i,j]) * W1_norm[j]
//     grid = (HH/(256*4) = 4, OO = 256), block = 256 threads
//     each thread owns one float4 of s[i, j:j+4]; streams 64 batch stores
// ---------------------------------------------------------------------------
__global__ void k_pert(const int* __restrict__ y,
                       const float* __restrict__ W2,
                       float* __restrict__ pert) {
    const int i  = blockIdx.y;
    const int j4 = blockIdx.x * 256 + threadIdx.x;   // float4 index within row
    const size_t joff = (size_t)j4 * 4;

    // stage y column y[:, i] as floats
    __shared__ float yf[BB];
    if (threadIdx.x < BB) yf[threadIdx.x] = (float)y[(size_t)threadIdx.x * OO + i];
    __syncthreads();

    // compute s = -EPS * sign(W2[i,j]) * W1_norm[j] once
    float4 w = reinterpret_cast<const float4*>(W2 + (size_t)i * HH)[j4];
    float4 n = reinterpret_cast<const float4*>(g_w1norm)[j4];
    float4 s;
    s.x = -EPS * ((w.x > 0.f) ? 1.f : (w.x < 0.f) ? -1.f : 0.f) * n.x;
    s.y = -EPS * ((w.y > 0.f) ? 1.f : (w.y < 0.f) ? -1.f : 0.f) * n.y;
    s.z = -EPS * ((w.z > 0.f) ? 1.f : (w.z < 0.f) ? -1.f : 0.f) * n.z;
    s.w = -EPS * ((w.w > 0.f) ? 1.f : (w.w < 0.f) ? -1.f : 0.f) * n.w;

    float* base = pert + (size_t)i * HH + joff;
    #pragma unroll 4
    for (int b = 0; b < BB; b++) {
        float yb = yf[b];
        float4 o;
        o.x = yb * s.x; o.y = yb * s.y; o.z = yb * s.z; o.w = yb * s.w;
        reinterpret_cast<float4*>(base + (size_t)b * OO * HH)[0] = o;
    }
}

// ---------------------------------------------------------------------------
// launch
// inputs (metadata order): x[0] (unused), y[1], W1[2], W2[3], bias1[4] (unused), bias2[5]
// out layout: nn_output [B*O] then pert [B*O*H]
// ---------------------------------------------------------------------------
extern "C" void kernel_launch(void* const* d_in, const int* in_sizes, int n_in,
                              void* d_out, int out_size) {
    const int*   y     = (const int*)d_in[1];
    const float* W1    = (const float*)d_in[2];
    const float* W2    = (const float*)d_in[3];
    const float* bias2 = (const float*)d_in[5];

    float* out_nn = (float*)d_out;
    float* pert   = out_nn + (size_t)BB * OO;

    k_w1norm<<<HH, 256>>>(W1);
    k_nnout<<<OO, 256>>>(W2, bias2, out_nn);
    dim3 grid(HH / (256 * 4), OO);
    k_pert<<<grid, 256>>>(y, W2, pert);
}

// round 2
// speedup vs baseline: 1.1490x; 1.1490x over previous
#include <cuda_runtime.h>

#define EPS 0.1f
#define BB 64
#define II 1024
#define HH 4096
#define OO 256

__device__ float g_w1norm[HH];

// ---------------------------------------------------------------------------
// K_pre: fused W1_norm + nn_output reductions (independent work, one launch)
//   blocks [0,512):   W1_norm — 8 warps/block, one warp per W1 row,
//                     8 independent LDG.128 per thread (MLP=8)
//   blocks [512,768): nn_output[i] = 4096*sum_j W2[i,j] + bias2[i], fanned
//                     out to all 64 batch rows (batch-independent)
// ---------------------------------------------------------------------------
__global__ void k_pre(const float* __restrict__ W1,
                      const float* __restrict__ W2,
                      const float* __restrict__ bias2,
                      float* __restrict__ out_nn) {
    const int bid = blockIdx.x;
    const int lid = threadIdx.x & 31;
    const int wid = threadIdx.x >> 5;

    if (bid < 512) {
        // ---- W1 row L1 norms: warp `wid` handles row bid*8+wid ----
        const int row = bid * 8 + wid;
        const float4* r = reinterpret_cast<const float4*>(W1 + (size_t)row * II);
        float4 v[8];
        #pragma unroll
        for (int k = 0; k < 8; k++) v[k] = r[lid + k * 32];  // 8 in-flight loads
        float s = 0.f;
        #pragma unroll
        for (int k = 0; k < 8; k++)
            s += fabsf(v[k].x) + fabsf(v[k].y) + fabsf(v[k].z) + fabsf(v[k].w);
        #pragma unroll
        for (int o = 16; o; o >>= 1) s += __shfl_down_sync(0xffffffffu, s, o);
        if (lid == 0) g_w1norm[row] = s;
    } else {
        // ---- nn_output row i ----
        const int i = bid - 512;
        const float4* r = reinterpret_cast<const float4*>(W2 + (size_t)i * HH);
        float4 v[4];
        #pragma unroll
        for (int k = 0; k < 4; k++) v[k] = r[threadIdx.x + k * 256];
        float s = 0.f;
        #pragma unroll
        for (int k = 0; k < 4; k++) s += v[k].x + v[k].y + v[k].z + v[k].w;

        __shared__ float sm[8];
        #pragma unroll
        for (int o = 16; o; o >>= 1) s += __shfl_down_sync(0xffffffffu, s, o);
        if (lid == 0) sm[wid] = s;
        __syncthreads();
        __shared__ float total;
        if (threadIdx.x < 8) {
            float t = sm[threadIdx.x];
            #pragma unroll
            for (int o = 4; o; o >>= 1) t += __shfl_down_sync(0xffu, t, o);
            if (threadIdx.x == 0) total = t * (float)HH + bias2[i];
        }
        __syncthreads();
        if (threadIdx.x < BB)
            out_nn[(size_t)threadIdx.x * OO + i] = total;
    }
}

// ---------------------------------------------------------------------------
// K_pert: pert[b,i,j] = -EPS * yf[b,i] * sign(W2[i,j]) * W1_norm[j]
//   grid = (HH/1024 = 4, OO = 256), block = 256
//   each thread owns one float4 of s[i, j:j+4]; streams 64 batch stores
//   (stores use .cs — 268 MB output, no reuse, keep it out of L2's way)
// ---------------------------------------------------------------------------
__global__ void k_pert(const int* __restrict__ y,
                       const float* __restrict__ W2,
                       float* __restrict__ pert) {
    const int i  = blockIdx.y;
    const int j4 = blockIdx.x * 256 + threadIdx.x;

    __shared__ float yf[BB];
    if (threadIdx.x < BB) yf[threadIdx.x] = (float)y[(size_t)threadIdx.x * OO + i];
    __syncthreads();

    float4 w = reinterpret_cast<const float4*>(W2 + (size_t)i * HH)[j4];
    float4 n = reinterpret_cast<const float4*>(g_w1norm)[j4];
    float4 s;
    s.x = -EPS * ((w.x > 0.f) ? 1.f : (w.x < 0.f) ? -1.f : 0.f) * n.x;
    s.y = -EPS * ((w.y > 0.f) ? 1.f : (w.y < 0.f) ? -1.f : 0.f) * n.y;
    s.z = -EPS * ((w.z > 0.f) ? 1.f : (w.z < 0.f) ? -1.f : 0.f) * n.z;
    s.w = -EPS * ((w.w > 0.f) ? 1.f : (w.w < 0.f) ? -1.f : 0.f) * n.w;

    float* base = pert + (size_t)i * HH + (size_t)j4 * 4;
    #pragma unroll 8
    for (int b = 0; b < BB; b++) {
        float yb = yf[b];
        float4 o;
        o.x = yb * s.x; o.y = yb * s.y; o.z = yb * s.z; o.w = yb * s.w;
        __stcs(reinterpret_cast<float4*>(base + (size_t)b * OO * HH), o);
    }
}

// ---------------------------------------------------------------------------
// launch
// inputs: x[0] (unused), y[1], W1[2], W2[3], bias1[4] (unused), bias2[5]
// out layout: nn_output [B*O] then pert [B*O*H]
// ---------------------------------------------------------------------------
extern "C" void kernel_launch(void* const* d_in, const int* in_sizes, int n_in,
                              void* d_out, int out_size) {
    const int*   y     = (const int*)d_in[1];
    const float* W1    = (const float*)d_in[2];
    const float* W2    = (const float*)d_in[3];
    const float* bias2 = (const float*)d_in[5];

    float* out_nn = (float*)d_out;
    float* pert   = out_nn + (size_t)BB * OO;

    k_pre<<<768, 256>>>(W1, W2, bias2, out_nn);
    dim3 grid(HH / 1024, OO);
    k_pert<<<grid, 256>>>(y, W2, pert);
}

// round 3
// speedup vs baseline: 1.2402x; 1.0794x over previous
#include <cuda_runtime.h>

#define EPS 0.1f
#define BB 64
#define II 1024
#define HH 4096
#define OO 256

__device__ float g_w1norm[HH];

// ---------------------------------------------------------------------------
// K1: W1_norm[j] = sum_i |W1[j,i]|
//   512 blocks x 256 threads; one warp per W1 row; 8 outstanding LDG.128/thread
// ---------------------------------------------------------------------------
__global__ void k_w1norm(const float* __restrict__ W1) {
    const int lid = threadIdx.x & 31;
    const int row = blockIdx.x * 8 + (threadIdx.x >> 5);
    const float4* r = reinterpret_cast<const float4*>(W1 + (size_t)row * II);
    float4 v[8];
    #pragma unroll
    for (int k = 0; k < 8; k++) v[k] = r[lid + k * 32];
    float s = 0.f;
    #pragma unroll
    for (int k = 0; k < 8; k++)
        s += fabsf(v[k].x) + fabsf(v[k].y) + fabsf(v[k].z) + fabsf(v[k].w);
    #pragma unroll
    for (int o = 16; o; o >>= 1) s += __shfl_down_sync(0xffffffffu, s, o);
    if (lid == 0) g_w1norm[row] = s;
}

// ---------------------------------------------------------------------------
// K2: fused nn_output + pert, 1D grid of 256 + 1024 blocks, 256 threads
//   bid <  256 : nn_output[b,i] = 4096*sum_j W2[i,j] + bias2[i]  (i = bid)
//                (4 MB read hides under the pert store stream)
//   bid >= 256 : pert[b,i,j] = -EPS*yf[b,i]*sign(W2[i,j])*W1_norm[j]
//                p = bid-256, bx = p&3 (j-chunk), i = p>>2
//                each thread owns one float4 of s; streams 64 STG.128 (.cs)
// ---------------------------------------------------------------------------
__global__ void k_main(const int* __restrict__ y,
                       const float* __restrict__ W2,
                       const float* __restrict__ bias2,
                       float* __restrict__ out_nn,
                       float* __restrict__ pert) {
    const int bid = blockIdx.x;
    const int lid = threadIdx.x & 31;
    const int wid = threadIdx.x >> 5;

    if (bid < 256) {
        // ---- nn_output row i ----
        const int i = bid;
        const float4* r = reinterpret_cast<const float4*>(W2 + (size_t)i * HH);
        float4 v[4];
        #pragma unroll
        for (int k = 0; k < 4; k++) v[k] = r[threadIdx.x + k * 256];
        float s = 0.f;
        #pragma unroll
        for (int k = 0; k < 4; k++) s += v[k].x + v[k].y + v[k].z + v[k].w;

        __shared__ float sm[8];
        #pragma unroll
        for (int o = 16; o; o >>= 1) s += __shfl_down_sync(0xffffffffu, s, o);
        if (lid == 0) sm[wid] = s;
        __syncthreads();
        __shared__ float total;
        if (threadIdx.x < 8) {
            float t = sm[threadIdx.x];
            #pragma unroll
            for (int o = 4; o; o >>= 1) t += __shfl_down_sync(0xffu, t, o);
            if (threadIdx.x == 0) total = t * (float)HH + bias2[i];
        }
        __syncthreads();
        if (threadIdx.x < BB)
            out_nn[(size_t)threadIdx.x * OO + i] = total;
        return;
    }

    // ---- pert ----
    const int p  = bid - 256;
    const int i  = p >> 2;
    const int j4 = (p & 3) * 256 + threadIdx.x;

    __shared__ float yf[BB];
    if (threadIdx.x < BB) yf[threadIdx.x] = (float)y[(size_t)threadIdx.x * OO + i];
    __syncthreads();

    float4 w = reinterpret_cast<const float4*>(W2 + (size_t)i * HH)[j4];
    float4 n = reinterpret_cast<const float4*>(g_w1norm)[j4];
    float4 s;
    s.x = -EPS * ((w.x > 0.f) ? 1.f : (w.x < 0.f) ? -1.f : 0.f) * n.x;
    s.y = -EPS * ((w.y > 0.f) ? 1.f : (w.y < 0.f) ? -1.f : 0.f) * n.y;
    s.z = -EPS * ((w.z > 0.f) ? 1.f : (w.z < 0.f) ? -1.f : 0.f) * n.z;
    s.w = -EPS * ((w.w > 0.f) ? 1.f : (w.w < 0.f) ? -1.f : 0.f) * n.w;

    float* base = pert + (size_t)i * HH + (size_t)j4 * 4;
    #pragma unroll 8
    for (int b = 0; b < BB; b++) {
        float yb = yf[b];
        float4 o;
        o.x = yb * s.x; o.y = yb * s.y; o.z = yb * s.z; o.w = yb * s.w;
        __stcs(reinterpret_cast<float4*>(base + (size_t)b * OO * HH), o);
    }
}

// ---------------------------------------------------------------------------
// launch
// inputs: x[0] (unused), y[1], W1[2], W2[3], bias1[4] (unused), bias2[5]
// out layout: nn_output [B*O] then pert [B*O*H]
// ---------------------------------------------------------------------------
extern "C" void kernel_launch(void* const* d_in, const int* in_sizes, int n_in,
                              void* d_out, int out_size) {
    const int*   y     = (const int*)d_in[1];
    const float* W1    = (const float*)d_in[2];
    const float* W2    = (const float*)d_in[3];
    const float* bias2 = (const float*)d_in[5];

    float* out_nn = (float*)d_out;
    float* pert   = out_nn + (size_t)BB * OO;

    k_w1norm<<<512, 256>>>(W1);
    k_main<<<256 + 1024, 256>>>(y, W2, bias2, out_nn, pert);
}